// round 5
// baseline (speedup 1.0000x reference)
#include <cuda_runtime.h>
#include <cuda_bf16.h>
#include <math.h>

#define B_   128
#define PP_  1024
#define LP_  128
#define H_   256

typedef unsigned long long u64;

// ---- device scratch ----
__device__ uint4 g_PeB[128 * 32];      // E_elem @ Wd1            (bf16, 32 uint4/row)
__device__ uint4 g_PaB[32  * 32];      // E_aa   @ Wd1            (bf16)
__device__ uint4 g_PbB[2   * 32];      // E_bb   @ Wd1 + bd1      (bf16)
__device__ float g_sPlig[16 * H_];     // silu(E_lig @ Wd1 + bd1) (f32)
__device__ float g_M    [512 * H_];    // [Wd2@Wa1_p ; Wd2@Wa1_l]
__device__ float g_bvec [H_];          // ba1 + bd2@(Wa1_p+Wa1_l)
__device__ float g_pool [2 * B_ * H_]; // per-batch SUMS of silu
__device__ float g_contact[B_ * 2];

// ---- packed f32x2 helpers (distance kernel) ----
__device__ __forceinline__ u64 f2_add(u64 a, u64 b){u64 r;asm("add.rn.f32x2 %0,%1,%2;":"=l"(r):"l"(a),"l"(b));return r;}
__device__ __forceinline__ u64 f2_mul(u64 a, u64 b){u64 r;asm("mul.rn.f32x2 %0,%1,%2;":"=l"(r):"l"(a),"l"(b));return r;}
__device__ __forceinline__ u64 f2_fma(u64 a, u64 b, u64 c){u64 r;asm("fma.rn.f32x2 %0,%1,%2,%3;":"=l"(r):"l"(a),"l"(b),"l"(c));return r;}
__device__ __forceinline__ u64 f2_pack(float x, float y){
    unsigned xi = __float_as_uint(x), yi = __float_as_uint(y);
    u64 r; asm("mov.b64 %0,{%1,%2};":"=l"(r):"r"(xi),"r"(yi)); return r;
}
__device__ __forceinline__ float2 f2_unpack(u64 a){
    unsigned lo, hi; asm("mov.b64 {%0,%1},%2;":"=r"(lo),"=r"(hi):"l"(a));
    return make_float2(__uint_as_float(lo), __uint_as_float(hi));
}

__device__ __forceinline__ __nv_bfloat162 asb(unsigned u){
    return *reinterpret_cast<__nv_bfloat162*>(&u);
}

// ================= Stage 1 =================
// [0,128)   : contact distances (independent of everything else)
// [128,301) : pm = bid-128: pm<45 -> project 178 embedding rows (x4) through Wd1
//                           else  -> M = Wd2 @ Wa1 slices (x4 rows)
// [301,309) : zero protein half of g_pool
// 309       : bvec
// 310       : out[b] = ba2
__global__ __launch_bounds__(256) void k_stage1(
    const float* __restrict__ Ee, const float* __restrict__ Ea,
    const float* __restrict__ Eb, const float* __restrict__ El,
    const float* __restrict__ Wd1, const float* __restrict__ bd1,
    const float* __restrict__ Wd2, const float* __restrict__ Wa1,
    const float* __restrict__ ba1, const float* __restrict__ bd2,
    const float* __restrict__ ba2, float* __restrict__ out,
    const float* __restrict__ ppos, const float* __restrict__ lpos)
{
    __shared__ __align__(16) char smbuf[14080];
    int bid = blockIdx.x, tid = threadIdx.x;
    if (bid < 128) {                       // ---- distances ----
        float* s_x = (float*)smbuf;
        float* s_y = s_x + PP_;
        float* s_z = s_y + PP_;
        float* s_half = s_z + PP_;
        float* s_d = s_half + 256;
        int b = bid;
        const float* pp = ppos + (size_t)b * PP_ * 3;
        for (int i = tid; i < PP_; i += 256) {
            s_x[i] = pp[3 * i]; s_y[i] = pp[3 * i + 1]; s_z[i] = pp[3 * i + 2];
        }
        __syncthreads();
        int lig = tid & (LP_ - 1), half = tid >> 7;
        const float* lp = lpos + ((size_t)b * LP_ + lig) * 3;
        float lx = lp[0], ly = lp[1], lz = lp[2];
        u64 NX = f2_pack(-lx, -lx), NY = f2_pack(-ly, -ly), NZ = f2_pack(-lz, -lz);
        const ulonglong2* sx = (const ulonglong2*)s_x + half * 128;
        const ulonglong2* sy = (const ulonglong2*)s_y + half * 128;
        const ulonglong2* sz = (const ulonglong2*)s_z + half * 128;
        float m0 = 3.4e38f, m1 = 3.4e38f, m2 = 3.4e38f, m3 = 3.4e38f;
        #pragma unroll 4
        for (int i = 0; i < 128; i++) {
            ulonglong2 X = sx[i], Y = sy[i], Z = sz[i];
            u64 dx = f2_add(X.x, NX), dy = f2_add(Y.x, NY), dz = f2_add(Z.x, NZ);
            u64 d2 = f2_fma(dz, dz, f2_fma(dy, dy, f2_mul(dx, dx)));
            float2 u = f2_unpack(d2);
            m0 = fminf(m0, u.x); m1 = fminf(m1, u.y);
            dx = f2_add(X.y, NX); dy = f2_add(Y.y, NY); dz = f2_add(Z.y, NZ);
            d2 = f2_fma(dz, dz, f2_fma(dy, dy, f2_mul(dx, dx)));
            u = f2_unpack(d2);
            m2 = fminf(m2, u.x); m3 = fminf(m3, u.y);
        }
        s_half[tid] = fminf(fminf(m0, m1), fminf(m2, m3));
        __syncthreads();
        if (tid < 128) s_d[tid] = sqrtf(fminf(s_half[tid], s_half[tid + 128]));
        __syncthreads();
        if (tid < 32) {
            float sum = 0.f, mn = 3.4e38f;
            #pragma unroll
            for (int i = 0; i < 4; i++) { float v = s_d[tid + 32 * i]; sum += v; mn = fminf(mn, v); }
            #pragma unroll
            for (int o = 16; o > 0; o >>= 1) {
                sum += __shfl_xor_sync(0xffffffffu, sum, o);
                mn = fminf(mn, __shfl_xor_sync(0xffffffffu, mn, o));
            }
            if (tid == 0) { g_contact[2 * b] = sum * (1.f / LP_); g_contact[2 * b + 1] = mn; }
        }
    } else if (bid < 301) {                // ---- projections / M ----
        float* s_at = (float*)smbuf;       // 4 KB: [k*4 + r]
        int pm = bid - 128;
        const float* src[4]; void* dst[4]; int mode[4], bias[4], valid[4];
        const float* Bp;
        if (pm < 45) {
            Bp = Wd1;
            int r0 = pm * 4;
            #pragma unroll
            for (int r = 0; r < 4; r++) {
                int g = r0 + r; valid[r] = (g < 178); bias[r] = 0;
                int gc = valid[r] ? g : 0;
                if      (gc < 128) { src[r] = Ee + gc * H_;       dst[r] = (__nv_bfloat16*)g_PeB + gc * H_;       mode[r] = 0; }
                else if (gc < 160) { src[r] = Ea + (gc-128) * H_; dst[r] = (__nv_bfloat16*)g_PaB + (gc-128) * H_; mode[r] = 0; }
                else if (gc < 162) { src[r] = Eb + (gc-160) * H_; dst[r] = (__nv_bfloat16*)g_PbB + (gc-160) * H_; mode[r] = 0; bias[r] = 1; }
                else               { src[r] = El + (gc-162) * H_; dst[r] = g_sPlig + (gc-162) * H_;               mode[r] = 1; bias[r] = 1; }
            }
        } else {
            int R = (pm - 45) * 4;
            Bp = (R < 256) ? Wa1 : (Wa1 + 256 * H_);
            #pragma unroll
            for (int r = 0; r < 4; r++) {
                src[r] = Wd2 + ((R + r) & 255) * H_;
                dst[r] = g_M + (R + r) * H_;
                mode[r] = 2; bias[r] = 0; valid[r] = 1;
            }
        }
        for (int idx = tid; idx < 4 * H_; idx += 256) {
            int k = idx >> 2, r = idx & 3;
            s_at[idx] = src[r][k];
        }
        __syncthreads();
        float a0 = 0, a1 = 0, a2 = 0, a3 = 0;
        const float4* sa4 = (const float4*)s_at;
        int j = tid;
        #pragma unroll 8
        for (int k = 0; k < H_; k++) {
            float w = Bp[k * H_ + j];
            float4 av = sa4[k];
            a0 += av.x * w; a1 += av.y * w; a2 += av.z * w; a3 += av.w * w;
        }
        float acc[4] = {a0, a1, a2, a3};
        float bj = bd1[j];
        #pragma unroll
        for (int r = 0; r < 4; r++) {
            if (!valid[r]) continue;
            float v = acc[r] + (bias[r] ? bj : 0.f);
            if (mode[r] == 2)      ((float*)dst[r])[j] = v;
            else if (mode[r] == 1) ((float*)dst[r])[j] = v / (1.f + expf(-v));
            else                   ((__nv_bfloat16*)dst[r])[j] = __float2bfloat16_rn(v);
        }
    } else if (bid < 309) {
        int base = (bid - 301) * 4096;
        for (int i = tid; i < 4096; i += 256) g_pool[base + i] = 0.f;
    } else if (bid == 309) {
        float* sb = (float*)smbuf;
        sb[tid] = bd2[tid];
        __syncthreads();
        float v = ba1[tid];
        #pragma unroll 8
        for (int k = 0; k < 512; k++) v += sb[k & 255] * Wa1[k * H_ + tid];
        g_bvec[tid] = v;
    } else {
        if (tid < 128) out[tid] = ba2[0];
    }
}

// ================= K2: fused gather + bf16 quad-silu + per-batch sums =================
// [0,1024)     protein pooling   (bf16x2 math)
// [1024,1152)  ligand histogram pooling
__global__ __launch_bounds__(256) void k_fused(
    const int* __restrict__ pelem, const int* __restrict__ paa,
    const int* __restrict__ pbb,   const int* __restrict__ pbatch,
    const int* __restrict__ ltype, const int* __restrict__ lbatch)
{
    __shared__ __align__(16) char smbuf[9728];
    int tid = threadIdx.x;
    if (blockIdx.x < 1024) {               // ---- protein: 128 rows per CTA ----
        float* s_red = (float*)smbuf;                       // 8 KB
        int* s_i0 = (int*)(smbuf + 8192);
        int* s_i1 = s_i0 + 128; int* s_i2 = s_i1 + 128;
        int warp = tid >> 5, lane = tid & 31;
        int row0 = blockIdx.x * 128;
        if (tid < 128) {
            s_i0[tid] = pelem[row0 + tid];
            s_i1[tid] = paa[row0 + tid];
            s_i2[tid] = pbb[row0 + tid];
        }
        int batch = pbatch[row0];
        uint4 b0 = g_PbB[lane], b1 = g_PbB[32 + lane];      // 2 bb rows in regs
        __syncthreads();
        __nv_bfloat162 C0 = __float2bfloat162_rn(0.5f);
        __nv_bfloat162 C1 = __float2bfloat162_rn(0.25f);
        __nv_bfloat162 Z  = __float2bfloat162_rn(0.f);
        __nv_bfloat162 acc0 = Z, acc1 = Z, acc2 = Z, acc3 = Z;
        #pragma unroll 4
        for (int i = 0; i < 16; i++) {
            int r = warp * 16 + i;
            int e = s_i0[r], a = s_i1[r];
            bool ib = s_i2[r] != 0;
            uint4 A  = g_PeB[(e << 5) + lane];
            uint4 Bv = g_PaB[(a << 5) + lane];
            unsigned cx = ib ? b1.x : b0.x, cy = ib ? b1.y : b0.y;
            unsigned cz = ib ? b1.z : b0.z, cw = ib ? b1.w : b0.w;
            __nv_bfloat162 s, t;
            s = __hadd2(__hadd2(asb(A.x), asb(Bv.x)), asb(cx));
            t = __hfma2(s, C1, C0); acc0 = __hfma2(s, t, acc0);
            s = __hadd2(__hadd2(asb(A.y), asb(Bv.y)), asb(cy));
            t = __hfma2(s, C1, C0); acc1 = __hfma2(s, t, acc1);
            s = __hadd2(__hadd2(asb(A.z), asb(Bv.z)), asb(cz));
            t = __hfma2(s, C1, C0); acc2 = __hfma2(s, t, acc2);
            s = __hadd2(__hadd2(asb(A.w), asb(Bv.w)), asb(cw));
            t = __hfma2(s, C1, C0); acc3 = __hfma2(s, t, acc3);
        }
        // lane holds cols [8*lane, 8*lane+8)
        float2 f0 = __bfloat1622float2(acc0), f1 = __bfloat1622float2(acc1);
        float2 f2v = __bfloat1622float2(acc2), f3 = __bfloat1622float2(acc3);
        float* my = s_red + warp * H_ + 8 * lane;
        ((float4*)my)[0] = make_float4(f0.x, f0.y, f1.x, f1.y);
        ((float4*)my)[1] = make_float4(f2v.x, f2v.y, f3.x, f3.y);
        __syncthreads();
        float sum = 0.f;
        #pragma unroll
        for (int w = 0; w < 8; w++) sum += s_red[w * H_ + tid];
        atomicAdd(&g_pool[batch * H_ + tid], sum);
    } else {                               // ---- ligand: histogram over 16 types ----
        int* s_cnt = (int*)smbuf;
        int bl = blockIdx.x - 1024;
        if (tid < 16) s_cnt[tid] = 0;
        __syncthreads();
        if (tid < 128) atomicAdd(&s_cnt[ltype[bl * 128 + tid]], 1);
        int batch = lbatch[bl * 128];
        __syncthreads();
        float sum = 0.f;
        #pragma unroll
        for (int t = 0; t < 16; t++) sum += (float)s_cnt[t] * g_sPlig[t * H_ + tid];
        g_pool[(B_ + batch) * H_ + tid] = sum;   // sole writer
    }
}

// ================= K3: affinity — full k-dot per tile, silu+dot epilogue in-CTA =================
// grid 128: bg = bid>>3 (16 groups of 8 batches), cg = bid&7 (col groups of 32)
__global__ __launch_bounds__(256) void k_aff(
    const float* __restrict__ Wa1, const float* __restrict__ Wa2,
    float* __restrict__ out)
{
    __shared__ float s_at[512 * 8];       // means transposed [k*8 + bb]  (16 KB)
    __shared__ float s_part[8 * 8 * 32];  // [ks][b][j]                   (8 KB)
    int bid = blockIdx.x, tid = threadIdx.x;
    int bg = bid >> 3, cg = bid & 7;
    for (int idx = tid; idx < 4096; idx += 256) {
        int k = idx >> 3, bb = idx & 7, b = bg * 8 + bb;
        s_at[idx] = (k < 256) ? g_pool[b * H_ + k] * (1.f / PP_)
                              : g_pool[(B_ + b) * H_ + (k - 256)] * (1.f / LP_);
    }
    __syncthreads();
    int j = tid & 31, ks = tid >> 5;
    int jj = cg * 32 + j;
    float a0 = 0, a1 = 0, a2 = 0, a3 = 0, a4 = 0, a5 = 0, a6 = 0, a7 = 0;
    const float* Mp = g_M + (ks * 64) * H_ + jj;
    const float* ap = s_at + (ks * 64) * 8;
    #pragma unroll 4
    for (int kl = 0; kl < 64; kl++) {
        float w = Mp[kl * H_];
        const float4* av = (const float4*)(ap + kl * 8);
        float4 v0 = av[0], v1 = av[1];
        a0 += v0.x * w; a1 += v0.y * w; a2 += v0.z * w; a3 += v0.w * w;
        a4 += v1.x * w; a5 += v1.y * w; a6 += v1.z * w; a7 += v1.w * w;
    }
    float* pb = s_part + ks * 256 + j;
    pb[0] = a0; pb[32] = a1; pb[64] = a2; pb[96] = a3;
    pb[128] = a4; pb[160] = a5; pb[192] = a6; pb[224] = a7;
    __syncthreads();
    // remap: warp wb -> batch, lane -> col
    int wb = tid >> 5, lane = tid & 31;
    float a = 0.f;
    #pragma unroll
    for (int k2 = 0; k2 < 8; k2++) a += s_part[k2 * 256 + wb * 32 + lane];
    int b = bg * 8 + wb, col = cg * 32 + lane;
    a += g_bvec[col]
       + g_contact[2 * b]     * Wa1[512 * H_ + col]
       + g_contact[2 * b + 1] * Wa1[513 * H_ + col];
    float h = a / (1.f + expf(-a));
    float v = h * Wa2[col];
    #pragma unroll
    for (int o = 16; o > 0; o >>= 1) v += __shfl_xor_sync(0xffffffffu, v, o);
    if (lane == 0) atomicAdd(&out[b], v);
}

extern "C" void kernel_launch(void* const* d_in, const int* in_sizes, int n_in,
                              void* d_out, int out_size) {
    const float* protein_pos     = (const float*)d_in[0];
    const float* ligand_pos      = (const float*)d_in[1];
    const int*   protein_element = (const int*)  d_in[2];
    const int*   protein_aa      = (const int*)  d_in[3];
    const int*   protein_bb      = (const int*)  d_in[4];
    const int*   ligand_type     = (const int*)  d_in[5];
    const int*   protein_batch   = (const int*)  d_in[6];
    const int*   ligand_batch    = (const int*)  d_in[7];
    const float* E_elem          = (const float*)d_in[8];
    const float* E_aa            = (const float*)d_in[9];
    const float* E_bb            = (const float*)d_in[10];
    const float* E_lig           = (const float*)d_in[11];
    const float* Wd1             = (const float*)d_in[12];
    const float* bd1             = (const float*)d_in[13];
    const float* Wd2             = (const float*)d_in[14];
    const float* bd2             = (const float*)d_in[15];
    const float* Wa1             = (const float*)d_in[16];
    const float* ba1             = (const float*)d_in[17];
    const float* Wa2             = (const float*)d_in[18];
    const float* ba2             = (const float*)d_in[19];
    float* out = (float*)d_out;

    k_stage1<<<311, 256>>>(E_elem, E_aa, E_bb, E_lig, Wd1, bd1, Wd2,
                           Wa1, ba1, bd2, ba2, out,
                           protein_pos, ligand_pos);
    k_fused <<<1152, 256>>>(protein_element, protein_aa, protein_bb,
                            protein_batch, ligand_type, ligand_batch);
    k_aff   <<<B_, 256>>>(Wa1, Wa2, out);
}